// round 10
// baseline (speedup 1.0000x reference)
#include <cuda_runtime.h>
#include <cuda_fp16.h>
#include <cstdint>

#define BB 8192
#define DD 256
#define TM 128
#define TN 128
#define NRB (BB/TM)          // 64 rowblocks
#define NCT (BB/TN)          // 64 col tiles
#define TOTW (NRB*NCT)       // 4096 tile visits
#define NCTA 148
#define WBASE (TOTW/NCTA)    // 27
#define WREM  (TOTW%NCTA)    // 100

static __device__ __align__(16) __half g_a16[BB*DD];
static __device__ __align__(16) __half g_p16[BB*DD];
static __device__ float    g_psum[BB];
static __device__ uint32_t g_pmaxu[BB];   // monotonic-mapped float
static __device__ float    g_diag[BB];

// dynamic smem: A @0 (64KB), P0 @64KB, P1 @128KB, stats @192KB
#define SM_A  0u
#define SM_P0 65536u
#define SM_P1 131072u
#define SM_ST 196608u
#define SMEM_BYTES (196608 + 6144)

#define INVT (1.0f/0.07f)
// exp((v-1)/T) = 2^(v*C1 - C1),  C1 = (1/T)*log2(e)
#define C1F 20.609929155556627f
#define NEGINF __int_as_float(0xff800000)

__device__ __forceinline__ uint32_t s2u(const void* p) {
    uint32_t r;
    asm("{ .reg .u64 t; cvta.to.shared.u64 t, %1; cvt.u32.u64 %0, t; }" : "=r"(r) : "l"(p));
    return r;
}

// monotonic float<->uint mapping (order-preserving incl. negatives)
__device__ __forceinline__ uint32_t fmap(float x) {
    uint32_t u = __float_as_uint(x);
    return (u & 0x80000000u) ? ~u : (u | 0x80000000u);
}
__device__ __forceinline__ float funmap(uint32_t m) {
    uint32_t u = (m & 0x80000000u) ? (m & 0x7FFFFFFFu) : ~m;
    return __uint_as_float(u);
}

// Load a 128x256 fp16 tile (64KB) with 512 threads: each thread one row-quarter
// (8 chunks of 16B). Row stride 512B; chunk' = chunk ^ (row & 7) xor swizzle.
__device__ __forceinline__ void load_tile(uint32_t s_dst, const __half* gtile, int tid) {
    const int row = tid >> 2;
    const int q   = tid & 3;
    const char* src = (const char*)(gtile + (size_t)row * DD) + q * 128;
    const uint32_t rbase = s_dst + (uint32_t)row * 512u;
    const uint32_t rx = (uint32_t)(row & 7);
    #pragma unroll
    for (int j = 0; j < 8; ++j) {
        uint32_t chunk = (uint32_t)(q * 8 + j);
        uint32_t d = rbase + ((chunk ^ rx) << 4);
        asm volatile("cp.async.cg.shared.global [%0], [%1], 16;"
                     :: "r"(d), "l"(src + j * 16));
    }
}

#define LDSM_X4(r0, r1, r2, r3, addr) \
    asm volatile("ldmatrix.sync.aligned.m8n8.x4.shared.b16 {%0,%1,%2,%3}, [%4];" \
                 : "=r"(r0), "=r"(r1), "=r"(r2), "=r"(r3) : "r"(addr))

#define MMA16816H(c, a, b0v, b1v) \
    asm volatile("mma.sync.aligned.m16n8k16.row.col.f16.f16.f16.f16 " \
                 "{%0,%1}, {%2,%3,%4,%5}, {%6,%7}, {%0,%1};" \
                 : "+r"((c)[0]), "+r"((c)[1]) \
                 : "r"((a)[0]), "r"((a)[1]), "r"((a)[2]), "r"((a)[3]), \
                   "r"(b0v), "r"(b1v))

// one epilogue unit: fold 4 values of accP (mf,h fixed, nf pair) into stats
__device__ __forceinline__ void epi_unit(
    int u, const uint32_t (&accP)[2][4][2],
    float (&sum)[2][2], float (&mx)[2][2], float (&dg)[2][2], const int (&rel)[2][2])
{
    const int mf = u >> 2, h = (u >> 1) & 1, np = u & 1;
    const int rr = rel[mf][h];
    #pragma unroll
    for (int k2 = 0; k2 < 2; ++k2) {
        const int nf = np * 2 + k2;
        float2 vv = __half22float2(*(const __half2*)&accP[mf][nf][h]);
        float ex0, ex1;
        asm("ex2.approx.f32 %0, %1;" : "=f"(ex0) : "f"(fmaf(vv.x, C1F, -C1F)));
        asm("ex2.approx.f32 %0, %1;" : "=f"(ex1) : "f"(fmaf(vv.y, C1F, -C1F)));
        sum[mf][h] += ex0 + ex1;
        bool d0 = (rr == nf * 8);
        bool d1 = (rr == nf * 8 + 1);
        mx[mf][h] = fmaxf(mx[mf][h], d0 ? NEGINF : vv.x);
        mx[mf][h] = fmaxf(mx[mf][h], d1 ? NEGINF : vv.y);
        if (d0) dg[mf][h] = vv.x;
        if (d1) dg[mf][h] = vv.y;
    }
}

// MMA over one 128x128 tile; if EPI, interleave the previous tile's epilogue.
template<bool EPI>
__device__ __forceinline__ void do_tile(
    uint32_t sb_pb, const uint32_t (&aBase)[2],
    uint32_t lrow, uint32_t khalf, uint32_t xorp, int warp_n,
    uint32_t (&accC)[2][4][2], const uint32_t (&accP)[2][4][2],
    float (&sum)[2][2], float (&mx)[2][2], float (&dg)[2][2], const int (&rel)[2][2])
{
    uint32_t bBase[2];
    #pragma unroll
    for (int nfp = 0; nfp < 2; ++nfp)
        bBase[nfp] = sb_pb + (uint32_t)(warp_n*32 + nfp*16 + (int)lrow) * 512u;

    #pragma unroll
    for (int mf = 0; mf < 2; ++mf)
        #pragma unroll
        for (int nf = 0; nf < 4; ++nf) { accC[mf][nf][0] = 0u; accC[mf][nf][1] = 0u; }

    #pragma unroll
    for (int ks = 0; ks < 16; ++ks) {
        const uint32_t coff = (((uint32_t)(2*ks) + khalf) ^ xorp) << 4;
        uint32_t a[2][4];
        #pragma unroll
        for (int mf = 0; mf < 2; ++mf)
            LDSM_X4(a[mf][0], a[mf][1], a[mf][2], a[mf][3], aBase[mf] + coff);
        uint32_t b[2][4];
        #pragma unroll
        for (int nfp = 0; nfp < 2; ++nfp)
            LDSM_X4(b[nfp][0], b[nfp][1], b[nfp][2], b[nfp][3], bBase[nfp] + coff);
        #pragma unroll
        for (int mf = 0; mf < 2; ++mf) {
            MMA16816H(accC[mf][0], a[mf], b[0][0], b[0][2]);
            MMA16816H(accC[mf][1], a[mf], b[0][1], b[0][3]);
            MMA16816H(accC[mf][2], a[mf], b[1][0], b[1][2]);
            MMA16816H(accC[mf][3], a[mf], b[1][1], b[1][3]);
        }
        if (EPI && (ks & 1)) epi_unit(ks >> 1, accP, sum, mx, dg, rel);
    }
}

// Warp-per-row: L2-normalize fp32 row -> fp16 row. Also resets per-row stats.
__global__ void nrm_kernel(const float* __restrict__ a, const float* __restrict__ p) {
    int lane = threadIdx.x & 31;
    int row = blockIdx.x * 16 + (threadIdx.x >> 5);
    if (blockIdx.y == 0 && lane == 0) {
        g_psum[row] = 0.f;
        g_pmaxu[row] = 0x007FFFFFu;   // fmap(-inf)
    }
    const float* src = (blockIdx.y ? p : a) + (size_t)row * DD + lane * 8;
    float4 v0 = *(const float4*)src;
    float4 v1 = *(const float4*)(src + 4);
    float ss = v0.x*v0.x + v0.y*v0.y + v0.z*v0.z + v0.w*v0.w
             + v1.x*v1.x + v1.y*v1.y + v1.z*v1.z + v1.w*v1.w;
    #pragma unroll
    for (int o = 16; o > 0; o >>= 1) ss += __shfl_xor_sync(0xffffffffu, ss, o);
    float sc = 1.0f / fmaxf(sqrtf(ss), 1e-12f);
    __half2 h[4];
    h[0] = __floats2half2_rn(v0.x*sc, v0.y*sc);
    h[1] = __floats2half2_rn(v0.z*sc, v0.w*sc);
    h[2] = __floats2half2_rn(v1.x*sc, v1.y*sc);
    h[3] = __floats2half2_rn(v1.z*sc, v1.w*sc);
    __half* dst = (blockIdx.y ? g_p16 : g_a16) + (size_t)row * DD + lane * 8;
    *(uint4*)dst = *(const uint4*)h;
}

__global__ __launch_bounds__(512, 1) void fused_kernel() {
    extern __shared__ char smem[];
    const uint32_t sb = s2u(smem);
    const int tid = threadIdx.x;
    const int lane = tid & 31, wid = tid >> 5;
    const int warp_m = wid >> 2;
    const int warp_n = wid & 3;
    const int c = blockIdx.x;

    // balanced contiguous range of tile visits
    const int start = WBASE * c + (c < WREM ? c : WREM);
    const int len   = WBASE + (c < WREM ? 1 : 0);
    const int rb0   = start >> 6;
    const int ct00  = start & 63;
    const int seg1  = (len < 64 - ct00) ? len : (64 - ct00);
    const int seg2  = len - seg1;

    const uint32_t lrow  = (uint32_t)(lane & 15);
    const uint32_t khalf = (uint32_t)(lane >> 4);
    const uint32_t xorp  = (uint32_t)(lane & 7);
    const int cloc = warp_n*32 + (lane & 3)*2;   // col offset of acc pair within tile

    uint32_t aBase[2];
    #pragma unroll
    for (int mf = 0; mf < 2; ++mf)
        aBase[mf] = sb + SM_A + (uint32_t)(warp_m*32 + mf*16 + (int)lrow) * 512u;

    float* sSum = (float*)(smem + SM_ST);        // [4][128]
    float* sMax = sSum + 512;
    float* sDg  = sMax + 512;

    uint32_t accA[2][4][2], accB[2][4][2];       // current / previous

    #pragma unroll 1
    for (int sg = 0; sg < 2; ++sg) {
        int rb, cbeg, cend;
        if (sg == 0) { rb = rb0; cbeg = ct00; cend = ct00 + seg1; }
        else         { if (seg2 <= 0) break; rb = rb0 + 1; cbeg = 0; cend = seg2; }
        const int R0 = rb * TM;

        // segment prologue: A + P(cbeg) [group 0], P(cbeg+1) [group 1]
        load_tile(sb + SM_A,  g_a16 + (size_t)R0 * DD, tid);
        load_tile(sb + SM_P0, g_p16 + (size_t)cbeg * TN * DD, tid);
        asm volatile("cp.async.commit_group;");
        if (cbeg + 1 < cend)
            load_tile(sb + SM_P1, g_p16 + (size_t)(cbeg + 1) * TN * DD, tid);
        asm volatile("cp.async.commit_group;");

        float sum[2][2], mx[2][2], dg[2][2];
        int grow[2][2], rel[2][2];
        #pragma unroll
        for (int mf = 0; mf < 2; ++mf)
            #pragma unroll
            for (int h = 0; h < 2; ++h) {
                sum[mf][h]=0.f; mx[mf][h]=NEGINF; dg[mf][h]=0.f;
                grow[mf][h] = R0 + warp_m*32 + mf*16 + (lane >> 2) + 8*h;
            }

        // ---- peeled first tile: MMA only ----
        {
            const int t = cbeg;
            if (t + 1 < cend) asm volatile("cp.async.wait_group 1;");
            else              asm volatile("cp.async.wait_group 0;");
            __syncthreads();
            do_tile<false>(sb + SM_P0, aBase, lrow, khalf, xorp, warp_n,
                           accB, accA, sum, mx, dg, rel);
            __syncthreads();
            if (t + 2 < cend) {
                load_tile(sb + SM_P0, g_p16 + (size_t)(t + 2) * TN * DD, tid);
                asm volatile("cp.async.commit_group;");
            } else {
                asm volatile("cp.async.commit_group;");
            }
            #pragma unroll
            for (int mf = 0; mf < 2; ++mf)
                #pragma unroll
                for (int h = 0; h < 2; ++h)
                    rel[mf][h] = grow[mf][h] - t*TN - cloc;
        }

        // ---- mainloop: MMA(t) interleaved with epilogue(t-1) ----
        #pragma unroll 1
        for (int t = cbeg + 1; t < cend; ++t) {
            const int i = t - cbeg;
            if (t + 1 < cend) asm volatile("cp.async.wait_group 1;");
            else              asm volatile("cp.async.wait_group 0;");
            __syncthreads();

            const uint32_t pb = (i & 1) ? SM_P1 : SM_P0;
            do_tile<true>(sb + pb, aBase, lrow, khalf, xorp, warp_n,
                          accA, accB, sum, mx, dg, rel);
            __syncthreads();
            if (t + 2 < cend) {
                load_tile(sb + pb, g_p16 + (size_t)(t + 2) * TN * DD, tid);
                asm volatile("cp.async.commit_group;");
            } else {
                asm volatile("cp.async.commit_group;");
            }

            // rotate: current becomes previous
            #pragma unroll
            for (int mf = 0; mf < 2; ++mf)
                #pragma unroll
                for (int nf = 0; nf < 4; ++nf) {
                    accB[mf][nf][0] = accA[mf][nf][0];
                    accB[mf][nf][1] = accA[mf][nf][1];
                }
            #pragma unroll
            for (int mf = 0; mf < 2; ++mf)
                #pragma unroll
                for (int h = 0; h < 2; ++h)
                    rel[mf][h] = grow[mf][h] - t*TN - cloc;
        }

        // drain epilogue of the last tile
        #pragma unroll
        for (int u = 0; u < 8; ++u) epi_unit(u, accB, sum, mx, dg, rel);

        // Quad reduction (lanes 4q..4q+3 share rows)
        #pragma unroll
        for (int mf = 0; mf < 2; ++mf) {
            #pragma unroll
            for (int h = 0; h < 2; ++h) {
                #pragma unroll
                for (int o = 1; o < 4; o <<= 1) {
                    sum[mf][h] += __shfl_xor_sync(0xffffffffu, sum[mf][h], o);
                    mx[mf][h]  = fmaxf(mx[mf][h], __shfl_xor_sync(0xffffffffu, mx[mf][h], o));
                    dg[mf][h]  += __shfl_xor_sync(0xffffffffu, dg[mf][h], o);
                }
            }
        }

        // Cross-warp_n combine via smem stats region, then atomic flush
        if ((lane & 3) == 0) {
            #pragma unroll
            for (int mf = 0; mf < 2; ++mf) {
                #pragma unroll
                for (int h = 0; h < 2; ++h) {
                    int rl = warp_m*32 + mf*16 + (lane >> 2) + 8*h;
                    sSum[warp_n*128 + rl] = sum[mf][h];
                    sMax[warp_n*128 + rl] = mx[mf][h];
                    sDg [warp_n*128 + rl] = dg[mf][h];
                }
            }
        }
        __syncthreads();
        if (tid < 128) {
            float S = 0.f, M = NEGINF, D = 0.f;
            #pragma unroll
            for (int w = 0; w < 4; ++w) {
                S += sSum[w*128 + tid];
                M = fmaxf(M, sMax[w*128 + tid]);
                D += sDg[w*128 + tid];
            }
            atomicAdd(&g_psum[R0 + tid], S);
            atomicMax(&g_pmaxu[R0 + tid], fmap(M));
            if (cbeg <= rb && rb < cend) g_diag[R0 + tid] = D;
        }
        __syncthreads();
    }
}

__global__ void finalize_kernel(float* out) {
    __shared__ double sm[256];
    double sloc = 0.0;
    for (int i = threadIdx.x; i < BB; i += 256) {
        float sum = g_psum[i];
        float m = funmap(g_pmaxu[i]);
        float total = sum + __expf((m - 1.0f) * INVT);
        sloc += (double)(INVT * (1.0f - g_diag[i]) + logf(total));
    }
    sm[threadIdx.x] = sloc;
    __syncthreads();
    for (int st = 128; st > 0; st >>= 1) {
        if (threadIdx.x < st) sm[threadIdx.x] += sm[threadIdx.x + st];
        __syncthreads();
    }
    if (threadIdx.x == 0) out[0] = (float)(sm[0] / (double)BB);
}

extern "C" void kernel_launch(void* const* d_in, const int* in_sizes, int n_in,
                              void* d_out, int out_size) {
    const float* anchor   = (const float*)d_in[0];
    const float* positive = (const float*)d_in[1];
    cudaFuncSetAttribute(fused_kernel, cudaFuncAttributeMaxDynamicSharedMemorySize, SMEM_BYTES);
    nrm_kernel<<<dim3(BB/16, 2), 512>>>(anchor, positive);
    fused_kernel<<<NCTA, 512, SMEM_BYTES>>>();
    finalize_kernel<<<1, 256>>>((float*)d_out);
}

// round 11
// speedup vs baseline: 1.3642x; 1.3642x over previous
#include <cuda_runtime.h>
#include <cuda_fp16.h>
#include <cstdint>

#define BB 8192
#define DD 256
#define TM 256
#define TN 64
#define NRB (BB/TM)          // 32 rowblocks
#define NCT (BB/TN)          // 128 col tiles
#define TOTW (NRB*NCT)       // 4096 tile visits
#define NCTA 148
#define WBASE (TOTW/NCTA)    // 27
#define WREM  (TOTW%NCTA)    // 100

static __device__ __align__(16) __half g_a16[BB*DD];
static __device__ __align__(16) __half g_p16[BB*DD];
static __device__ float    g_psum[BB];
static __device__ uint32_t g_pmaxu[BB];   // monotonic-mapped float
static __device__ float    g_diag[BB];

// dynamic smem: A @0 (128KB), P0 @128KB (32KB), P1, stats @192KB
#define SM_A  0u
#define SM_P0 131072u
#define SM_P1 163840u
#define SM_ST 196608u
#define SMEM_BYTES (196608 + 6144)

#define INVT (1.0f/0.07f)
// exp((v-1)/T) = 2^(v*C1 - C1),  C1 = (1/T)*log2(e)
#define C1F 20.609929155556627f
#define NEGINF __int_as_float(0xff800000)

__device__ __forceinline__ uint32_t s2u(const void* p) {
    uint32_t r;
    asm("{ .reg .u64 t; cvta.to.shared.u64 t, %1; cvt.u32.u64 %0, t; }" : "=r"(r) : "l"(p));
    return r;
}

// monotonic float<->uint mapping (order-preserving incl. negatives)
__device__ __forceinline__ uint32_t fmap(float x) {
    uint32_t u = __float_as_uint(x);
    return (u & 0x80000000u) ? ~u : (u | 0x80000000u);
}
__device__ __forceinline__ float funmap(uint32_t m) {
    uint32_t u = (m & 0x80000000u) ? (m & 0x7FFFFFFFu) : ~m;
    return __uint_as_float(u);
}

// A tile: 256 rows x 256 fp16 (128KB). 512 threads, 16 chunks of 16B each.
// Row stride 512B; chunk' = chunk ^ (row & 7) xor swizzle.
__device__ __forceinline__ void load_tileA(uint32_t s_dst, const __half* gtile, int tid) {
    const int row = tid >> 1;          // 0..255
    const int h   = tid & 1;
    const char* src = (const char*)(gtile + (size_t)row * DD) + h * 256;
    const uint32_t rbase = s_dst + (uint32_t)row * 512u;
    const uint32_t rx = (uint32_t)(row & 7);
    #pragma unroll
    for (int j = 0; j < 16; ++j) {
        uint32_t chunk = (uint32_t)(h * 16 + j);
        uint32_t d = rbase + ((chunk ^ rx) << 4);
        asm volatile("cp.async.cg.shared.global [%0], [%1], 16;"
                     :: "r"(d), "l"(src + j * 16));
    }
}

// P tile: 64 rows x 256 fp16 (32KB). 512 threads, 4 chunks of 16B each.
__device__ __forceinline__ void load_tileP(uint32_t s_dst, const __half* gtile, int tid) {
    const int row = tid >> 3;          // 0..63
    const int q   = tid & 7;
    const char* src = (const char*)(gtile + (size_t)row * DD) + q * 64;
    const uint32_t rbase = s_dst + (uint32_t)row * 512u;
    const uint32_t rx = (uint32_t)(row & 7);
    #pragma unroll
    for (int j = 0; j < 4; ++j) {
        uint32_t chunk = (uint32_t)(q * 4 + j);
        uint32_t d = rbase + ((chunk ^ rx) << 4);
        asm volatile("cp.async.cg.shared.global [%0], [%1], 16;"
                     :: "r"(d), "l"(src + j * 16));
    }
}

#define LDSM_X4(r0, r1, r2, r3, addr) \
    asm volatile("ldmatrix.sync.aligned.m8n8.x4.shared.b16 {%0,%1,%2,%3}, [%4];" \
                 : "=r"(r0), "=r"(r1), "=r"(r2), "=r"(r3) : "r"(addr))

#define MMA16816H(c, a, b0v, b1v) \
    asm volatile("mma.sync.aligned.m16n8k16.row.col.f16.f16.f16.f16 " \
                 "{%0,%1}, {%2,%3,%4,%5}, {%6,%7}, {%0,%1};" \
                 : "+r"((c)[0]), "+r"((c)[1]) \
                 : "r"((a)[0]), "r"((a)[1]), "r"((a)[2]), "r"((a)[3]), \
                   "r"(b0v), "r"(b1v))

// Warp-per-row: L2-normalize fp32 row -> fp16 row. Also resets per-row stats.
__global__ void nrm_kernel(const float* __restrict__ a, const float* __restrict__ p) {
    int lane = threadIdx.x & 31;
    int row = blockIdx.x * 16 + (threadIdx.x >> 5);
    if (blockIdx.y == 0 && lane == 0) {
        g_psum[row] = 0.f;
        g_pmaxu[row] = 0x007FFFFFu;   // fmap(-inf)
        g_diag[row] = 0.f;
    }
    const float* src = (blockIdx.y ? p : a) + (size_t)row * DD + lane * 8;
    float4 v0 = *(const float4*)src;
    float4 v1 = *(const float4*)(src + 4);
    float ss = v0.x*v0.x + v0.y*v0.y + v0.z*v0.z + v0.w*v0.w
             + v1.x*v1.x + v1.y*v1.y + v1.z*v1.z + v1.w*v1.w;
    #pragma unroll
    for (int o = 16; o > 0; o >>= 1) ss += __shfl_xor_sync(0xffffffffu, ss, o);
    float sc = 1.0f / fmaxf(sqrtf(ss), 1e-12f);
    __half2 h[4];
    h[0] = __floats2half2_rn(v0.x*sc, v0.y*sc);
    h[1] = __floats2half2_rn(v0.z*sc, v0.w*sc);
    h[2] = __floats2half2_rn(v1.x*sc, v1.y*sc);
    h[3] = __floats2half2_rn(v1.z*sc, v1.w*sc);
    __half* dst = (blockIdx.y ? g_p16 : g_a16) + (size_t)row * DD + lane * 8;
    *(uint4*)dst = *(const uint4*)h;
}

__global__ __launch_bounds__(512, 1) void fused_kernel() {
    extern __shared__ char smem[];
    const uint32_t sb = s2u(smem);
    const int tid = threadIdx.x;
    const int lane = tid & 31, wid = tid >> 5;
    const int warp_m = wid >> 1;          // 0..7
    const int warp_n = wid & 1;           // 0..1
    const int c = blockIdx.x;

    // balanced contiguous range of tile visits
    const int start = WBASE * c + (c < WREM ? c : WREM);
    const int len   = WBASE + (c < WREM ? 1 : 0);
    const int rb0   = start >> 7;         // /NCT
    const int ct00  = start & 127;
    const int seg1  = (len < NCT - ct00) ? len : (NCT - ct00);
    const int seg2  = len - seg1;

    const uint32_t lrow  = (uint32_t)(lane & 15);
    const uint32_t khalf = (uint32_t)(lane >> 4);
    const uint32_t xorp  = (uint32_t)(lane & 7);
    const float NEG = NEGINF;

    uint32_t aBase[2];
    #pragma unroll
    for (int mf = 0; mf < 2; ++mf)
        aBase[mf] = sb + SM_A + (uint32_t)(warp_m*32 + mf*16 + (int)lrow) * 512u;

    float* sSum = (float*)(smem + SM_ST);        // [2][256]
    float* sMax = sSum + 512;
    float* sDg  = sMax + 512;

    #pragma unroll 1
    for (int sg = 0; sg < 2; ++sg) {
        int rb, cbeg, cend;
        if (sg == 0) { rb = rb0; cbeg = ct00; cend = ct00 + seg1; }
        else         { if (seg2 <= 0) break; rb = rb0 + 1; cbeg = 0; cend = seg2; }
        const int R0 = rb * TM;

        // segment prologue: A + P(cbeg) [group 0], P(cbeg+1) [group 1]
        load_tileA(sb + SM_A, g_a16 + (size_t)R0 * DD, tid);
        load_tileP(sb + SM_P0, g_p16 + (size_t)cbeg * TN * DD, tid);
        asm volatile("cp.async.commit_group;");
        if (cbeg + 1 < cend)
            load_tileP(sb + SM_P1, g_p16 + (size_t)(cbeg + 1) * TN * DD, tid);
        asm volatile("cp.async.commit_group;");

        float sum[2][2], mx[2][2], dg[2][2];
        int grow[2][2];
        #pragma unroll
        for (int mf = 0; mf < 2; ++mf)
            #pragma unroll
            for (int h = 0; h < 2; ++h) {
                sum[mf][h]=0.f; mx[mf][h]=NEG; dg[mf][h]=0.f;
                grow[mf][h] = R0 + warp_m*32 + mf*16 + (lane >> 2) + 8*h;
            }

        #pragma unroll 1
        for (int t = cbeg; t < cend; ++t) {
            const int i = t - cbeg;
            if (t + 1 < cend) asm volatile("cp.async.wait_group 1;");
            else              asm volatile("cp.async.wait_group 0;");
            __syncthreads();

            const uint32_t pb = (i & 1) ? SM_P1 : SM_P0;
            uint32_t bBase[2];
            #pragma unroll
            for (int nfp = 0; nfp < 2; ++nfp)
                bBase[nfp] = sb + pb + (uint32_t)(warp_n*32 + nfp*16 + (int)lrow) * 512u;

            uint32_t acc[2][4][2];
            #pragma unroll
            for (int mf = 0; mf < 2; ++mf)
                #pragma unroll
                for (int nf = 0; nf < 4; ++nf) { acc[mf][nf][0] = 0u; acc[mf][nf][1] = 0u; }

            #pragma unroll
            for (int ks = 0; ks < 16; ++ks) {
                const uint32_t coff = (((uint32_t)(2*ks) + khalf) ^ xorp) << 4;
                uint32_t a[2][4];
                #pragma unroll
                for (int mf = 0; mf < 2; ++mf)
                    LDSM_X4(a[mf][0], a[mf][1], a[mf][2], a[mf][3], aBase[mf] + coff);
                uint32_t b[2][4];
                #pragma unroll
                for (int nfp = 0; nfp < 2; ++nfp)
                    LDSM_X4(b[nfp][0], b[nfp][1], b[nfp][2], b[nfp][3], bBase[nfp] + coff);
                #pragma unroll
                for (int mf = 0; mf < 2; ++mf) {
                    MMA16816H(acc[mf][0], a[mf], b[0][0], b[0][2]);
                    MMA16816H(acc[mf][1], a[mf], b[0][1], b[0][3]);
                    MMA16816H(acc[mf][2], a[mf], b[1][0], b[1][2]);
                    MMA16816H(acc[mf][3], a[mf], b[1][1], b[1][3]);
                }
            }

            __syncthreads();
            if (t + 2 < cend) {
                load_tileP(sb + pb, g_p16 + (size_t)(t + 2) * TN * DD, tid);
                asm volatile("cp.async.commit_group;");
            } else {
                asm volatile("cp.async.commit_group;");   // keep group count in step
            }

            // Epilogue: fold 256x64 tile into streaming stats (registers only)
            if ((t >> 2) != rb) {
                #pragma unroll
                for (int mf = 0; mf < 2; ++mf) {
                    #pragma unroll
                    for (int h = 0; h < 2; ++h) {
                        float lsum = 0.f, lmx = mx[mf][h];
                        #pragma unroll
                        for (int nf = 0; nf < 4; ++nf) {
                            float2 vv = __half22float2(*(__half2*)&acc[mf][nf][h]);
                            float ex0, ex1;
                            asm("ex2.approx.f32 %0, %1;" : "=f"(ex0) : "f"(fmaf(vv.x, C1F, -C1F)));
                            asm("ex2.approx.f32 %0, %1;" : "=f"(ex1) : "f"(fmaf(vv.y, C1F, -C1F)));
                            lsum += ex0 + ex1;
                            lmx = fmaxf(lmx, fmaxf(vv.x, vv.y));
                        }
                        sum[mf][h] += lsum;
                        mx[mf][h] = lmx;
                    }
                }
            } else {
                const int cb0 = t*TN + warp_n*32 + (lane & 3)*2;
                #pragma unroll
                for (int mf = 0; mf < 2; ++mf) {
                    #pragma unroll
                    for (int h = 0; h < 2; ++h) {
                        const int r = grow[mf][h];
                        float lsum = 0.f;
                        #pragma unroll
                        for (int nf = 0; nf < 4; ++nf) {
                            float2 vv = __half22float2(*(__half2*)&acc[mf][nf][h]);
                            float ex0, ex1;
                            asm("ex2.approx.f32 %0, %1;" : "=f"(ex0) : "f"(fmaf(vv.x, C1F, -C1F)));
                            asm("ex2.approx.f32 %0, %1;" : "=f"(ex1) : "f"(fmaf(vv.y, C1F, -C1F)));
                            lsum += ex0 + ex1;
                            bool d0 = ((cb0 + nf*8    ) == r);
                            bool d1 = ((cb0 + nf*8 + 1) == r);
                            mx[mf][h] = fmaxf(mx[mf][h], d0 ? NEG : vv.x);
                            mx[mf][h] = fmaxf(mx[mf][h], d1 ? NEG : vv.y);
                            if (d0) dg[mf][h] = vv.x;
                            if (d1) dg[mf][h] = vv.y;
                        }
                        sum[mf][h] += lsum;
                    }
                }
            }
        }

        // Quad reduction (lanes 4q..4q+3 share rows)
        #pragma unroll
        for (int mf = 0; mf < 2; ++mf) {
            #pragma unroll
            for (int h = 0; h < 2; ++h) {
                #pragma unroll
                for (int o = 1; o < 4; o <<= 1) {
                    sum[mf][h] += __shfl_xor_sync(0xffffffffu, sum[mf][h], o);
                    mx[mf][h]  = fmaxf(mx[mf][h], __shfl_xor_sync(0xffffffffu, mx[mf][h], o));
                    dg[mf][h]  += __shfl_xor_sync(0xffffffffu, dg[mf][h], o);
                }
            }
        }

        // Cross-warp_n combine via smem stats region, then atomic flush
        if ((lane & 3) == 0) {
            #pragma unroll
            for (int mf = 0; mf < 2; ++mf) {
                #pragma unroll
                for (int h = 0; h < 2; ++h) {
                    int rl = warp_m*32 + mf*16 + (lane >> 2) + 8*h;   // 0..255
                    sSum[warp_n*256 + rl] = sum[mf][h];
                    sMax[warp_n*256 + rl] = mx[mf][h];
                    sDg [warp_n*256 + rl] = dg[mf][h];
                }
            }
        }
        __syncthreads();
        if (tid < 256) {
            float S = sSum[tid] + sSum[256 + tid];
            float M = fmaxf(sMax[tid], sMax[256 + tid]);
            float D = sDg[tid] + sDg[256 + tid];
            atomicAdd(&g_psum[R0 + tid], S);
            atomicMax(&g_pmaxu[R0 + tid], fmap(M));
            if (D != 0.f) atomicAdd(&g_diag[R0 + tid], D);
        }
        __syncthreads();
    }
}

__global__ void finalize_kernel(float* out) {
    __shared__ double sm[256];
    double sloc = 0.0;
    for (int i = threadIdx.x; i < BB; i += 256) {
        float sum = g_psum[i];
        float m = funmap(g_pmaxu[i]);
        float total = sum + __expf((m - 1.0f) * INVT);
        sloc += (double)(INVT * (1.0f - g_diag[i]) + logf(total));
    }
    sm[threadIdx.x] = sloc;
    __syncthreads();
    for (int st = 128; st > 0; st >>= 1) {
        if (threadIdx.x < st) sm[threadIdx.x] += sm[threadIdx.x + st];
        __syncthreads();
    }
    if (threadIdx.x == 0) out[0] = (float)(sm[0] / (double)BB);
}

extern "C" void kernel_launch(void* const* d_in, const int* in_sizes, int n_in,
                              void* d_out, int out_size) {
    const float* anchor   = (const float*)d_in[0];
    const float* positive = (const float*)d_in[1];
    cudaFuncSetAttribute(fused_kernel, cudaFuncAttributeMaxDynamicSharedMemorySize, SMEM_BYTES);
    nrm_kernel<<<dim3(BB/16, 2), 512>>>(anchor, positive);
    fused_kernel<<<NCTA, 512, SMEM_BYTES>>>();
    finalize_kernel<<<1, 256>>>((float*)d_out);
}